// round 15
// baseline (speedup 1.0000x reference)
#include <cuda_runtime.h>
#include <stdint.h>
#include <math.h>

#define Bc     4
#define Sc     16
#define Dc     1024
#define DNc    2048
#define Kc     8
#define NBc    4
#define VOCABc 151936
#define NBLK   512
#define NTHR   128
#define STAGES 5
#define PFD    3

// ---------------- device state (static; no allocation) ----------------
__device__ float g_Vst[2 * NBc * Bc * DNc];
__device__ float g_u[NBc * Bc * Dc];
__device__ float g_xbuf[2][Bc * Dc];
__device__ float g_sp[Bc * DNc];
__device__ float g_frames[Kc * Bc * Dc];
__device__ float g_decoded[Bc * Dc];
__device__ float g_hh[Bc * Dc];
__device__ float g_pV[3 * NBc * Bc * DNc / 1];   // [m*4+i][b][n] V-side partial sums (393KB)

__device__ unsigned g_bar_count;
__device__ volatile unsigned g_bar_gen;

// ---------------- helpers ----------------
__device__ __forceinline__ float sigmf_(float a) { return 1.0f / (1.0f + expf(-a)); }
__device__ __forceinline__ float softplusf_(float a) {
    return fmaxf(a, 0.0f) + log1pf(expf(-fabsf(a)));
}
__device__ __forceinline__ float warp_sum(float v) {
    v += __shfl_xor_sync(0xffffffffu, v, 16);
    v += __shfl_xor_sync(0xffffffffu, v, 8);
    v += __shfl_xor_sync(0xffffffffu, v, 4);
    v += __shfl_xor_sync(0xffffffffu, v, 2);
    v += __shfl_xor_sync(0xffffffffu, v, 1);
    return v;
}
__device__ __forceinline__ float dot4(float acc, float4 wv, float4 av) {
    return fmaf(wv.x, av.x, fmaf(wv.y, av.y, fmaf(wv.z, av.z, fmaf(wv.w, av.w, acc))));
}

// Grid barrier; all 512 blocks co-resident (launch_bounds(128,4), smem ~41KB -> 4/SM).
__device__ __forceinline__ void grid_sync() {
    __syncthreads();
    if (threadIdx.x == 0) {
        __threadfence();
        unsigned gen = g_bar_gen;
        if (atomicAdd(&g_bar_count, 1u) == (unsigned)(gridDim.x - 1)) {
            g_bar_count = 0;
            __threadfence();
            g_bar_gen = gen + 1;
        } else {
            while (g_bar_gen == gen) __nanosleep(64);
        }
        __threadfence();
    }
    __syncthreads();
}

// ---------------- cp.async machinery ----------------
__device__ __forceinline__ void cp16(uint32_t dst, const void* src, uint64_t pol) {
    asm volatile("cp.async.cg.shared.global.L2::cache_hint [%0], [%1], 16, %2;"
                 :: "r"(dst), "l"(src), "l"(pol) : "memory");
}
__device__ __forceinline__ void cp_commit() {
    asm volatile("cp.async.commit_group;" ::: "memory");
}
template <int N>
__device__ __forceinline__ void cp_wait() {
    asm volatile("cp.async.wait_group %0;" :: "n"(N) : "memory");
}
__device__ __forceinline__ uint64_t pol_evict_first() {
    uint64_t p; asm("createpolicy.fractional.L2::evict_first.b64 %0;" : "=l"(p)); return p;
}
__device__ __forceinline__ uint64_t pol_evict_last() {
    uint64_t p; asm("createpolicy.fractional.L2::evict_last.b64 %0;" : "=l"(p)); return p;
}

// ---- chained-pipeline macros ----
#define ISS4(SLOT, WP, LD, IDX, POL) do {                                          \
    const float* _wp = (WP); const size_t _ldw = (LD); const int _ix = (IDX);      \
    cp16(sb + (uint32_t)(((SLOT)*4+0)*32+lane)*16u, (const float4*)(_wp) + _ix, POL);            \
    cp16(sb + (uint32_t)(((SLOT)*4+1)*32+lane)*16u, (const float4*)(_wp+_ldw) + _ix, POL);       \
    cp16(sb + (uint32_t)(((SLOT)*4+2)*32+lane)*16u, (const float4*)(_wp+2*_ldw) + _ix, POL);     \
    cp16(sb + (uint32_t)(((SLOT)*4+3)*32+lane)*16u, (const float4*)(_wp+3*_ldw) + _ix, POL);     \
    cp_commit();                                                                   \
} while (0)

#define ISS2(SLOT, WP, LD, IDX, POL) do {                                          \
    const float* _wp = (WP); const size_t _ldw = (LD); const int _ix = (IDX);      \
    cp16(sb + (uint32_t)(((SLOT)*4+0)*32+lane)*16u, (const float4*)(_wp) + _ix, POL);            \
    cp16(sb + (uint32_t)(((SLOT)*4+1)*32+lane)*16u, (const float4*)(_wp+_ldw) + _ix, POL);       \
    cp_commit();                                                                   \
} while (0)

#define ISS_NONE() cp_commit()

#define CONS4(SLOT, IDX, P0, P1, P2, P3) do {                                      \
    const int _ix = (IDX);                                                         \
    float4 _b0 = __ldg((const float4*)(P0) + _ix);                                 \
    float4 _b1 = __ldg((const float4*)(P1) + _ix);                                 \
    float4 _b2 = __ldg((const float4*)(P2) + _ix);                                 \
    float4 _b3 = __ldg((const float4*)(P3) + _ix);                                 \
    cp_wait<PFD>();                                                                \
    float4 _q0 = wbuf[((SLOT)*4+0)*32+lane];                                       \
    float4 _q1 = wbuf[((SLOT)*4+1)*32+lane];                                       \
    float4 _q2 = wbuf[((SLOT)*4+2)*32+lane];                                       \
    float4 _q3 = wbuf[((SLOT)*4+3)*32+lane];                                       \
    acc[0]  = dot4(acc[0],  _q0, _b0); acc[1]  = dot4(acc[1],  _q0, _b1);          \
    acc[2]  = dot4(acc[2],  _q0, _b2); acc[3]  = dot4(acc[3],  _q0, _b3);          \
    acc[4]  = dot4(acc[4],  _q1, _b0); acc[5]  = dot4(acc[5],  _q1, _b1);          \
    acc[6]  = dot4(acc[6],  _q1, _b2); acc[7]  = dot4(acc[7],  _q1, _b3);          \
    acc[8]  = dot4(acc[8],  _q2, _b0); acc[9]  = dot4(acc[9],  _q2, _b1);          \
    acc[10] = dot4(acc[10], _q2, _b2); acc[11] = dot4(acc[11], _q2, _b3);          \
    acc[12] = dot4(acc[12], _q3, _b0); acc[13] = dot4(acc[13], _q3, _b1);          \
    acc[14] = dot4(acc[14], _q3, _b2); acc[15] = dot4(acc[15], _q3, _b3);          \
} while (0)

#define CONS2(SLOT, IDX, P0, P1, P2, P3) do {                                      \
    const int _ix = (IDX);                                                         \
    float4 _b0 = __ldg((const float4*)(P0) + _ix);                                 \
    float4 _b1 = __ldg((const float4*)(P1) + _ix);                                 \
    float4 _b2 = __ldg((const float4*)(P2) + _ix);                                 \
    float4 _b3 = __ldg((const float4*)(P3) + _ix);                                 \
    cp_wait<PFD>();                                                                \
    float4 _q0 = wbuf[((SLOT)*4+0)*32+lane];                                       \
    float4 _q1 = wbuf[((SLOT)*4+1)*32+lane];                                       \
    acc[0] = dot4(acc[0], _q0, _b0); acc[1] = dot4(acc[1], _q0, _b1);              \
    acc[2] = dot4(acc[2], _q0, _b2); acc[3] = dot4(acc[3], _q0, _b3);              \
    acc[4] = dot4(acc[4], _q1, _b0); acc[5] = dot4(acc[5], _q1, _b1);              \
    acc[6] = dot4(acc[6], _q1, _b2); acc[7] = dot4(acc[7], _q1, _b3);              \
} while (0)

#define ZERO(N) do { _Pragma("unroll") for (int _q = 0; _q < (N); ++_q) acc[_q] = 0.0f; } while (0)

// plain pass for tiny enc/dec GEMVs
template <int NR, int NF4>
__device__ __forceinline__ void passN(
    const float* __restrict__ wrow0, int ldw,
    const float* __restrict__ px0, const float* __restrict__ px1,
    const float* __restrict__ px2, const float* __restrict__ px3,
    int warp, int lane, float* acc)
{
    const float4* a0 = (const float4*)px0;
    const float4* a1 = (const float4*)px1;
    const float4* a2 = (const float4*)px2;
    const float4* a3 = (const float4*)px3;
    int cbase = warp * NF4 * 32 + lane;
#pragma unroll
    for (int it = 0; it < NF4; ++it) {
        int idx = cbase + it * 32;
        float4 b0 = __ldg(a0 + idx);
        float4 b1 = __ldg(a1 + idx);
        float4 b2 = __ldg(a2 + idx);
        float4 b3 = __ldg(a3 + idx);
#pragma unroll
        for (int r = 0; r < NR; ++r) {
            const float4* wr = (const float4*)(wrow0 + (size_t)r * ldw);
            float4 q = __ldcs(wr + idx);
            acc[r * 4 + 0] = dot4(acc[r * 4 + 0], q, b0);
            acc[r * 4 + 1] = dot4(acc[r * 4 + 1], q, b1);
            acc[r * 4 + 2] = dot4(acc[r * 4 + 2], q, b2);
            acc[r * 4 + 3] = dot4(acc[r * 4 + 3], q, b3);
        }
    }
}

template <int NA>
__device__ __forceinline__ void reduceN(const float* acc, float (*sh)[4], int warp, int lane) {
#pragma unroll
    for (int i = 0; i < NA; ++i) {
        float v = warp_sum(acc[i]);
        if (lane == 0) sh[i][warp] = v;
    }
}

__device__ __forceinline__ const float* xsel_ptr(int sel) {
    return (sel < Kc) ? (g_frames + (size_t)sel * Bc * Dc) : g_xbuf[sel - Kc];
}

// ---------------- the whole model as ONE persistent kernel ----------------
__global__ void __launch_bounds__(NTHR, 4) snn_mono_kernel(
    const int* __restrict__ tok, const float* __restrict__ embed,
    const float* __restrict__ norm_w,
    const float* __restrict__ encW, const float* __restrict__ encb,
    const float* __restrict__ decW, const float* __restrict__ decb,
    const float* __restrict__ Win, const float* __restrict__ WbX,
    const float* __restrict__ WaX, const float* __restrict__ WtX,
    const float* __restrict__ WbV, const float* __restrict__ WaV,
    const float* __restrict__ WtV,
    const float* __restrict__ b_beta, const float* __restrict__ b_alpha,
    const float* __restrict__ b_th,
    const float* __restrict__ Wgate, const float* __restrict__ Wskip,
    const float* __restrict__ Wout,
    const float* __restrict__ plif_w, const float* __restrict__ out_vth,
    float* __restrict__ out)
{
    const int blk  = blockIdx.x;
    const int tid  = threadIdx.x;
    const int warp = tid >> 5, lane = tid & 31;
    __shared__ float sh[4][16][4];
    __shared__ float4 cpbuf[4][STAGES * 4 * 32];   // 40KB
    float4* wbuf = cpbuf[warp];
    const uint32_t sb = (uint32_t)__cvta_generic_to_shared(wbuf);
    const uint64_t polS = pol_evict_first();   // one-shot streams (blk1, lmhead)
    const uint64_t polK = pol_evict_last();    // re-read weights (blk2)

    for (int i = blk * NTHR + tid; i < NBc * Bc * DNc; i += NBLK * NTHR) g_Vst[i] = 0.0f;
    for (int i = blk * NTHR + tid; i < NBc * Bc * Dc;  i += NBLK * NTHR) g_u[i]   = 0.0f;
    grid_sync();

    const int xI0 = warp * 64 + lane,  xI1 = xI0 + 32;
    const int vI0 = warp * 128 + lane, vI1 = vI0 + 32, vI2 = vI0 + 64, vI3 = vI0 + 96;

    int par = 0;
    for (int t = 0; t < Sc; ++t) {
        // ================= encoder: 2 rows/block =================
        {
            int j0 = blk * 2;
            const float* e0 = embed + (size_t)__ldg(tok + 0 * Sc + t) * Dc;
            const float* e1 = embed + (size_t)__ldg(tok + 1 * Sc + t) * Dc;
            const float* e2 = embed + (size_t)__ldg(tok + 2 * Sc + t) * Dc;
            const float* e3 = embed + (size_t)__ldg(tok + 3 * Sc + t) * Dc;
            float acc[8];
            ZERO(8);
            passN<2, 2>(encW + (size_t)j0 * Dc, Dc, e0, e1, e2, e3, warp, lane, acc);
            reduceN<8>(acc, sh[0], warp, lane);
            __syncthreads();
            if (tid < 8) {
                int r = tid >> 2, b = tid & 3;
                int j = j0 + r;
                float s = sh[0][tid][0] + sh[0][tid][1] + sh[0][tid][2] + sh[0][tid][3];
                float res = sigmf_(s + encb[j]);
#pragma unroll
                for (int k = 0; k < Kc; ++k) {
                    float bit = (res >= 0.5f) ? 1.0f : 0.0f;
                    g_frames[((size_t)k * Bc + b) * Dc + j] = bit;
                    res = (res - 0.5f * bit) * 2.0f;
                }
                g_decoded[b * Dc + j] = 0.0f;
            }
        }
        grid_sync();

        // ================= K frames x NB blocks =================
        for (int k = 0; k < Kc; ++k) {
            // ---- Phase A: V-side partials for ALL 4 blocks, barrier-free ----
            // 6144 4-row groups over 512 CTAs = 12 groups (48 tiles) per CTA,
            // one continuous cp.async chain. pV[m*4+i][b][n] = sum_w warpsum(V-side).
            {
                const float* vbasePar = g_Vst + (size_t)par * NBc * Bc * DNc;
                float acc[16];
                ZERO(16);
                int slotI = 0, slotC = 0;
#pragma unroll
                for (int p = 0; p < PFD; ++p) {
                    int g = blk * 12 + (p >> 2); int s = p & 3;
                    int mi = g >> 9, rb = g & 511, m = mi >> 2, ii = mi & 3;
                    const float* W = (m == 0 ? WbV : (m == 1 ? WaV : WtV))
                                   + ((size_t)ii * DNc + (size_t)rb * 4) * DNc;
                    ISS4(slotI, W, DNc, vI0 + s * 32, polS);
                    slotI = (slotI + 1 == STAGES) ? 0 : slotI + 1;
                }
                for (int T = 0; T < 48; ++T) {
                    int Tf = T + PFD;
                    if (Tf < 48) {
                        int g = blk * 12 + (Tf >> 2); int s = Tf & 3;
                        int mi = g >> 9, rb = g & 511, m = mi >> 2, ii = mi & 3;
                        const float* W = (m == 0 ? WbV : (m == 1 ? WaV : WtV))
                                       + ((size_t)ii * DNc + (size_t)rb * 4) * DNc;
                        ISS4(slotI, W, DNc, vI0 + s * 32, polS);
                    } else {
                        ISS_NONE();
                    }
                    slotI = (slotI + 1 == STAGES) ? 0 : slotI + 1;
                    {
                        int g = blk * 12 + (T >> 2); int s = T & 3;
                        int ii = (g >> 9) & 3;
                        const float* vb = vbasePar + (size_t)ii * Bc * DNc;
                        CONS4(slotC, vI0 + s * 32, vb, vb + DNc, vb + 2 * DNc, vb + 3 * DNc);
                    }
                    slotC = (slotC + 1 == STAGES) ? 0 : slotC + 1;
                    if ((T & 3) == 3) {
                        int j = T >> 2;
                        int g = blk * 12 + j;
                        int mi = g >> 9, rb = g & 511;
                        reduceN<16>(acc, sh[j & 3], warp, lane);
                        __syncthreads();
                        if (tid < 16) {
                            int r = tid >> 2, b = tid & 3;
                            int n = rb * 4 + r;
                            float s2 = sh[j & 3][tid][0] + sh[j & 3][tid][1]
                                     + sh[j & 3][tid][2] + sh[j & 3][tid][3];
                            g_pV[((size_t)mi * Bc + b) * DNc + n] = s2;
                        }
                        ZERO(16);
                    }
                }
            }
            grid_sync();

            int xin = k;
            for (int i = 0; i < NBc; ++i) {
                // ---- blk1 serial: X-side only (8 tiles) + pV epilogue ----
                {
                    size_t n0 = (size_t)blk * 4;
                    const float* x  = xsel_ptr(xin);
                    const float* Vi = g_Vst + ((size_t)par * NBc + i) * Bc * DNc;
                    float*       Vo = g_Vst + ((size_t)(par ^ 1) * NBc + i) * Bc * DNc;
                    const float* x0 = x;            const float* x1 = x + Dc;
                    const float* x2 = x + 2 * Dc;   const float* x3 = x + 3 * Dc;
                    size_t rX = ((size_t)i * DNc + n0) * Dc;
                    const float* WBX = WbX + rX;
                    const float* WAX = WaX + rX;
                    const float* WTX = WtX + rX;
                    const float* WIN = Win + rX;
                    float acc[16];

                    ZERO(16);
                    ISS4(0, WBX, Dc, xI0, polS);
                    ISS4(1, WBX, Dc, xI1, polS);
                    ISS4(2, WAX, Dc, xI0, polS);
                    ISS4(3, WAX, Dc, xI1, polS); CONS4(0, xI0, x0, x1, x2, x3);
                    ISS4(4, WTX, Dc, xI0, polS); CONS4(1, xI1, x0, x1, x2, x3);
                    reduceN<16>(acc, sh[0], warp, lane); ZERO(16);
                    ISS4(0, WTX, Dc, xI1, polS); CONS4(2, xI0, x0, x1, x2, x3);
                    ISS4(1, WIN, Dc, xI0, polS); CONS4(3, xI1, x0, x1, x2, x3);
                    reduceN<16>(acc, sh[1], warp, lane); ZERO(16);
                    ISS4(2, WIN, Dc, xI1, polS); CONS4(4, xI0, x0, x1, x2, x3);
                    ISS_NONE();                  CONS4(0, xI1, x0, x1, x2, x3);
                    reduceN<16>(acc, sh[2], warp, lane); ZERO(16);
                    ISS_NONE();                  CONS4(1, xI0, x0, x1, x2, x3);
                    ISS_NONE();                  CONS4(2, xI1, x0, x1, x2, x3);
                    reduceN<16>(acc, sh[3], warp, lane);

                    __syncthreads();
                    if (tid < 16) {
                        int r = tid >> 2, b = tid & 3;
                        size_t n = n0 + r;
                        float pB = sh[0][tid][0] + sh[0][tid][1] + sh[0][tid][2] + sh[0][tid][3];
                        float pA = sh[1][tid][0] + sh[1][tid][1] + sh[1][tid][2] + sh[1][tid][3];
                        float pT = sh[2][tid][0] + sh[2][tid][1] + sh[2][tid][2] + sh[2][tid][3];
                        float pI = sh[3][tid][0] + sh[3][tid][1] + sh[3][tid][2] + sh[3][tid][3];
                        float vB = g_pV[((size_t)(0 * NBc + i) * Bc + b) * DNc + n];
                        float vA = g_pV[((size_t)(1 * NBc + i) * Bc + b) * DNc + n];
                        float vT = g_pV[((size_t)(2 * NBc + i) * Bc + b) * DNc + n];
                        float beta  = sigmf_(pB + vB + b_beta[(size_t)i * DNc + n]);
                        float alpha = sigmf_(pA + vA + b_alpha[(size_t)i * DNc + n]);
                        float vth   = 0.1f + softplusf_(pT + vT + b_th[(size_t)i * DNc + n]);
                        float vold  = Vi[(size_t)b * DNc + n];
                        float vnew  = beta * vold + alpha * pI;
                        float spv   = ((vnew - vth) >= 0.0f) ? 1.0f : 0.0f;
                        Vo[(size_t)b * DNc + n]   = vnew - spv * vth;
                        g_sp[(size_t)b * DNc + n] = spv;
                    }
                }
                grid_sync();

                // ---- blk2: 2 rows/block, chained pipeline over 8 tiles ----
                {
                    int xo = Kc + (i & 1);
                    size_t j0 = (size_t)blk * 2;
                    const float* x = xsel_ptr(xin);
                    float* xout = g_xbuf[xo - Kc];
                    const float* x0 = x;           const float* x1 = x + Dc;
                    const float* x2 = x + 2 * Dc;  const float* x3 = x + 3 * Dc;
                    const float* s0 = g_sp;            const float* s1 = g_sp + DNc;
                    const float* s2 = g_sp + 2 * DNc;  const float* s3 = g_sp + 3 * DNc;
                    size_t rD = ((size_t)i * Dc + j0) * Dc;
                    size_t rN = ((size_t)i * Dc + j0) * DNc;
                    const float* WG = Wgate + rD;
                    const float* WS = Wskip + rD;
                    const float* WO = Wout + rN;
                    float acc[8];

                    ZERO(8);
                    ISS2(0, WG, Dc,  xI0, polK);
                    ISS2(1, WG, Dc,  xI1, polK);
                    ISS2(2, WS, Dc,  xI0, polK);
                    ISS2(3, WS, Dc,  xI1, polK); CONS2(0, xI0, x0, x1, x2, x3);
                    ISS2(4, WO, DNc, vI0, polK); CONS2(1, xI1, x0, x1, x2, x3);
                    reduceN<8>(acc, sh[0], warp, lane); ZERO(8);
                    ISS2(0, WO, DNc, vI1, polK); CONS2(2, xI0, x0, x1, x2, x3);
                    ISS2(1, WO, DNc, vI2, polK); CONS2(3, xI1, x0, x1, x2, x3);
                    reduceN<8>(acc, sh[1], warp, lane); ZERO(8);
                    ISS2(2, WO, DNc, vI3, polK); CONS2(4, vI0, s0, s1, s2, s3);
                    ISS_NONE();                  CONS2(0, vI1, s0, s1, s2, s3);
                    ISS_NONE();                  CONS2(1, vI2, s0, s1, s2, s3);
                    ISS_NONE();                  CONS2(2, vI3, s0, s1, s2, s3);
                    reduceN<8>(acc, sh[2], warp, lane);

                    __syncthreads();
                    if (tid < 8) {
                        int r = tid >> 2, b = tid & 3;
                        size_t j = j0 + r;
                        float g  = sh[0][tid][0] + sh[0][tid][1] + sh[0][tid][2] + sh[0][tid][3];
                        float sk = sh[1][tid][0] + sh[1][tid][1] + sh[1][tid][2] + sh[1][tid][3];
                        float o  = sh[2][tid][0] + sh[2][tid][1] + sh[2][tid][2] + sh[2][tid][3];
                        float cur = sigmf_(g) * o + sk;
                        float tau = sigmf_(plif_w[i]);
                        float vt  = out_vth[i];
                        size_t ui = ((size_t)i * Bc + b) * Dc + j;
                        float uu = g_u[ui];
                        uu = uu + (cur - uu) * tau;
                        float so = ((uu - vt) >= 0.0f) ? 1.0f : 0.0f;
                        g_u[ui] = (1.0f - so) * uu;
                        xout[(size_t)b * Dc + j] = so;
                        if (i == NBc - 1) {
                            float wk = 1.0f / (float)(1 << (k + 1));
                            g_decoded[(size_t)b * Dc + j] += wk * so;
                        }
                    }
                    xin = xo;
                }
                grid_sync();
            }
            par ^= 1;
        }

        // ================= decoder: 2 rows/block =================
        {
            size_t j0 = (size_t)blk * 2;
            const float* d0 = g_decoded;           const float* d1 = g_decoded + Dc;
            const float* d2 = g_decoded + 2 * Dc;  const float* d3 = g_decoded + 3 * Dc;
            float acc[8];
            ZERO(8);
            passN<2, 2>(decW + j0 * Dc, Dc, d0, d1, d2, d3, warp, lane, acc);
            reduceN<8>(acc, sh[0], warp, lane);
            __syncthreads();
            if (tid < 8) {
                int r = tid >> 2, b = tid & 3;
                size_t j = j0 + r;
                float s = sh[0][tid][0] + sh[0][tid][1] + sh[0][tid][2] + sh[0][tid][3];
                g_hh[(size_t)b * Dc + j] = s + decb[j];
            }
        }
        grid_sync();

        // ================= RMSNorm (block 0 only) =================
        if (blk == 0) {
            __shared__ float srstd[Bc];
            if (warp < Bc) {
                float s = 0.0f;
                for (int j = lane; j < Dc; j += 32) {
                    float v = g_hh[warp * Dc + j];
                    s = fmaf(v, v, s);
                }
                s = warp_sum(s);
                if (lane == 0) srstd[warp] = 1.0f / sqrtf(s / (float)Dc + 1e-6f);
            }
            __syncthreads();
            for (int idx = tid; idx < Bc * Dc; idx += NTHR) {
                g_hh[idx] = g_hh[idx] * norm_w[idx & (Dc - 1)] * srstd[idx >> 10];
            }
        }
        grid_sync();

        // ================= LM head: chained over all iterations =================
        {
            const float* h0 = g_hh;           const float* h1 = g_hh + Dc;
            const float* h2 = g_hh + 2 * Dc;  const float* h3 = g_hh + 3 * Dc;
            const int nit = ((size_t)74 * (NBLK * 4) + (size_t)blk * 4 < VOCABc) ? 75 : 74;
            const int TT  = nit * 2;
            float acc[16];
            ZERO(16);
#pragma unroll
            for (int tau = 0; tau < PFD; ++tau) {
                int it2 = tau >> 1, sub = tau & 1;
                const float* wb2 = embed + ((size_t)it2 * (NBLK * 4) + (size_t)blk * 4) * Dc;
                ISS4(tau, wb2, Dc, xI0 + sub * 32, polS);
            }
            for (int tau = 0; tau < TT; ++tau) {
                int tf = tau + PFD;
                if (tf < TT) {
                    int it2 = tf >> 1, sub = tf & 1;
                    const float* wb2 = embed + ((size_t)it2 * (NBLK * 4) + (size_t)blk * 4) * Dc;
                    ISS4(tf % STAGES, wb2, Dc, xI0 + sub * 32, polS);
                } else {
                    ISS_NONE();
                }
                CONS4(tau % STAGES, xI0 + (tau & 1) * 32, h0, h1, h2, h3);
                if (tau & 1) {
                    reduceN<16>(acc, sh[0], warp, lane);
                    __syncthreads();
                    if (tid < 16) {
                        int r = tid >> 2, b = tid & 3;
                        size_t v0 = (size_t)(tau >> 1) * (NBLK * 4) + (size_t)blk * 4;
                        float s = sh[0][tid][0] + sh[0][tid][1] + sh[0][tid][2] + sh[0][tid][3];
                        out[((size_t)b * Sc + t) * VOCABc + v0 + r] = s;
                    }
                    __syncthreads();
                    ZERO(16);
                }
            }
        }
        // no grid_sync needed: the sync after enc(t+1) orders lmhead(t)
        // against the next writer of g_hh (dec at t+1).
    }
}

// ---------------- host driver: ONE graph node ----------------
extern "C" void kernel_launch(void* const* d_in, const int* in_sizes, int n_in,
                              void* d_out, int out_size)
{
    (void)in_sizes; (void)n_in; (void)out_size;
    snn_mono_kernel<<<NBLK, NTHR>>>(
        (const int*)d_in[0],  (const float*)d_in[1],  (const float*)d_in[2],
        (const float*)d_in[3], (const float*)d_in[4], (const float*)d_in[5],
        (const float*)d_in[6], (const float*)d_in[7], (const float*)d_in[8],
        (const float*)d_in[9], (const float*)d_in[10], (const float*)d_in[11],
        (const float*)d_in[12], (const float*)d_in[13], (const float*)d_in[14],
        (const float*)d_in[15], (const float*)d_in[16], (const float*)d_in[17],
        (const float*)d_in[18], (const float*)d_in[19], (const float*)d_in[20],
        (const float*)d_in[21], (float*)d_out);
}

// round 16
// speedup vs baseline: 1.1414x; 1.1414x over previous
#include <cuda_runtime.h>
#include <stdint.h>
#include <math.h>

#define Bc     4
#define Sc     16
#define Dc     1024
#define DNc    2048
#define Kc     8
#define NBc    4
#define VOCABc 151936
#define NBLK   512
#define NTHR   128
#define STAGES 5
#define PFD    3

// ---------------- device state (static; no allocation) ----------------
__device__ float g_Vst[2 * NBc * Bc * DNc];
__device__ float g_u[NBc * Bc * Dc];
__device__ float g_xbuf[2][Bc * Dc];
__device__ float g_sp[Bc * DNc];
__device__ float g_frames[Kc * Bc * Dc];
__device__ float g_decoded[Bc * Dc];
__device__ float g_hh[2][Bc * Dc];            // double buffer: token t -> g_hh[t&1]

__device__ unsigned g_bar_count;
__device__ volatile unsigned g_bar_gen;

// ---------------- helpers ----------------
__device__ __forceinline__ float sigmf_(float a) { return 1.0f / (1.0f + expf(-a)); }
__device__ __forceinline__ float softplusf_(float a) {
    return fmaxf(a, 0.0f) + log1pf(expf(-fabsf(a)));
}
__device__ __forceinline__ float warp_sum(float v) {
    v += __shfl_xor_sync(0xffffffffu, v, 16);
    v += __shfl_xor_sync(0xffffffffu, v, 8);
    v += __shfl_xor_sync(0xffffffffu, v, 4);
    v += __shfl_xor_sync(0xffffffffu, v, 2);
    v += __shfl_xor_sync(0xffffffffu, v, 1);
    return v;
}
__device__ __forceinline__ float dot4(float acc, float4 wv, float4 av) {
    return fmaf(wv.x, av.x, fmaf(wv.y, av.y, fmaf(wv.z, av.z, fmaf(wv.w, av.w, acc))));
}

// Grid barrier; all 512 blocks co-resident (launch_bounds(128,4), smem ~41KB -> 4/SM).
__device__ __forceinline__ void grid_sync() {
    __syncthreads();
    if (threadIdx.x == 0) {
        __threadfence();
        unsigned gen = g_bar_gen;
        if (atomicAdd(&g_bar_count, 1u) == (unsigned)(gridDim.x - 1)) {
            g_bar_count = 0;
            __threadfence();
            g_bar_gen = gen + 1;
        } else {
            while (g_bar_gen == gen) __nanosleep(64);
        }
        __threadfence();
    }
    __syncthreads();
}

// ---------------- cp.async machinery ----------------
__device__ __forceinline__ void cp16(uint32_t dst, const void* src, uint64_t pol) {
    asm volatile("cp.async.cg.shared.global.L2::cache_hint [%0], [%1], 16, %2;"
                 :: "r"(dst), "l"(src), "l"(pol) : "memory");
}
__device__ __forceinline__ void cp_commit() {
    asm volatile("cp.async.commit_group;" ::: "memory");
}
template <int N>
__device__ __forceinline__ void cp_wait() {
    asm volatile("cp.async.wait_group %0;" :: "n"(N) : "memory");
}
__device__ __forceinline__ uint64_t pol_evict_first() {
    uint64_t p; asm("createpolicy.fractional.L2::evict_first.b64 %0;" : "=l"(p)); return p;
}
__device__ __forceinline__ uint64_t pol_evict_last() {
    uint64_t p; asm("createpolicy.fractional.L2::evict_last.b64 %0;" : "=l"(p)); return p;
}

// ---- chained-pipeline macros ----
#define ISS4(SLOT, WP, LD, IDX, POL) do {                                          \
    const float* _wp = (WP); const size_t _ldw = (LD); const int _ix = (IDX);      \
    cp16(sb + (uint32_t)(((SLOT)*4+0)*32+lane)*16u, (const float4*)(_wp) + _ix, POL);            \
    cp16(sb + (uint32_t)(((SLOT)*4+1)*32+lane)*16u, (const float4*)(_wp+_ldw) + _ix, POL);       \
    cp16(sb + (uint32_t)(((SLOT)*4+2)*32+lane)*16u, (const float4*)(_wp+2*_ldw) + _ix, POL);     \
    cp16(sb + (uint32_t)(((SLOT)*4+3)*32+lane)*16u, (const float4*)(_wp+3*_ldw) + _ix, POL);     \
    cp_commit();                                                                   \
} while (0)

#define ISS2(SLOT, WP, LD, IDX, POL) do {                                          \
    const float* _wp = (WP); const size_t _ldw = (LD); const int _ix = (IDX);      \
    cp16(sb + (uint32_t)(((SLOT)*4+0)*32+lane)*16u, (const float4*)(_wp) + _ix, POL);            \
    cp16(sb + (uint32_t)(((SLOT)*4+1)*32+lane)*16u, (const float4*)(_wp+_ldw) + _ix, POL);       \
    cp_commit();                                                                   \
} while (0)

#define ISS_NONE() cp_commit()

#define FMA16(Q0, Q1, Q2, Q3, B0, B1, B2, B3) do {                                 \
    acc[0]  = dot4(acc[0],  Q0, B0); acc[1]  = dot4(acc[1],  Q0, B1);              \
    acc[2]  = dot4(acc[2],  Q0, B2); acc[3]  = dot4(acc[3],  Q0, B3);              \
    acc[4]  = dot4(acc[4],  Q1, B0); acc[5]  = dot4(acc[5],  Q1, B1);              \
    acc[6]  = dot4(acc[6],  Q1, B2); acc[7]  = dot4(acc[7],  Q1, B3);              \
    acc[8]  = dot4(acc[8],  Q2, B0); acc[9]  = dot4(acc[9],  Q2, B1);              \
    acc[10] = dot4(acc[10], Q2, B2); acc[11] = dot4(acc[11], Q2, B3);              \
    acc[12] = dot4(acc[12], Q3, B0); acc[13] = dot4(acc[13], Q3, B1);              \
    acc[14] = dot4(acc[14], Q3, B2); acc[15] = dot4(acc[15], Q3, B3);              \
} while (0)

#define CONS4(SLOT, IDX, P0, P1, P2, P3) do {                                      \
    const int _ix = (IDX);                                                         \
    float4 _b0 = __ldg((const float4*)(P0) + _ix);                                 \
    float4 _b1 = __ldg((const float4*)(P1) + _ix);                                 \
    float4 _b2 = __ldg((const float4*)(P2) + _ix);                                 \
    float4 _b3 = __ldg((const float4*)(P3) + _ix);                                 \
    cp_wait<PFD>();                                                                \
    float4 _q0 = wbuf[((SLOT)*4+0)*32+lane];                                       \
    float4 _q1 = wbuf[((SLOT)*4+1)*32+lane];                                       \
    float4 _q2 = wbuf[((SLOT)*4+2)*32+lane];                                       \
    float4 _q3 = wbuf[((SLOT)*4+3)*32+lane];                                       \
    FMA16(_q0, _q1, _q2, _q3, _b0, _b1, _b2, _b3);                                 \
} while (0)

#define CONS2(SLOT, IDX, P0, P1, P2, P3) do {                                      \
    const int _ix = (IDX);                                                         \
    float4 _b0 = __ldg((const float4*)(P0) + _ix);                                 \
    float4 _b1 = __ldg((const float4*)(P1) + _ix);                                 \
    float4 _b2 = __ldg((const float4*)(P2) + _ix);                                 \
    float4 _b3 = __ldg((const float4*)(P3) + _ix);                                 \
    cp_wait<PFD>();                                                                \
    float4 _q0 = wbuf[((SLOT)*4+0)*32+lane];                                       \
    float4 _q1 = wbuf[((SLOT)*4+1)*32+lane];                                       \
    acc[0] = dot4(acc[0], _q0, _b0); acc[1] = dot4(acc[1], _q0, _b1);              \
    acc[2] = dot4(acc[2], _q0, _b2); acc[3] = dot4(acc[3], _q0, _b3);              \
    acc[4] = dot4(acc[4], _q1, _b0); acc[5] = dot4(acc[5], _q1, _b1);              \
    acc[6] = dot4(acc[6], _q1, _b2); acc[7] = dot4(acc[7], _q1, _b3);              \
} while (0)

#define ZERO(N) do { _Pragma("unroll") for (int _q = 0; _q < (N); ++_q) acc[_q] = 0.0f; } while (0)

// plain pass for tiny enc/dec GEMVs
template <int NR, int NF4>
__device__ __forceinline__ void passN(
    const float* __restrict__ wrow0, int ldw,
    const float* __restrict__ px0, const float* __restrict__ px1,
    const float* __restrict__ px2, const float* __restrict__ px3,
    int warp, int lane, float* acc)
{
    const float4* a0 = (const float4*)px0;
    const float4* a1 = (const float4*)px1;
    const float4* a2 = (const float4*)px2;
    const float4* a3 = (const float4*)px3;
    int cbase = warp * NF4 * 32 + lane;
#pragma unroll
    for (int it = 0; it < NF4; ++it) {
        int idx = cbase + it * 32;
        float4 b0 = __ldg(a0 + idx);
        float4 b1 = __ldg(a1 + idx);
        float4 b2 = __ldg(a2 + idx);
        float4 b3 = __ldg(a3 + idx);
#pragma unroll
        for (int r = 0; r < NR; ++r) {
            const float4* wr = (const float4*)(wrow0 + (size_t)r * ldw);
            float4 q = __ldcs(wr + idx);
            acc[r * 4 + 0] = dot4(acc[r * 4 + 0], q, b0);
            acc[r * 4 + 1] = dot4(acc[r * 4 + 1], q, b1);
            acc[r * 4 + 2] = dot4(acc[r * 4 + 2], q, b2);
            acc[r * 4 + 3] = dot4(acc[r * 4 + 3], q, b3);
        }
    }
}

template <int NA>
__device__ __forceinline__ void reduceN(const float* acc, float (*sh)[4], int warp, int lane) {
#pragma unroll
    for (int i = 0; i < NA; ++i) {
        float v = warp_sum(acc[i]);
        if (lane == 0) sh[i][warp] = v;
    }
}

__device__ __forceinline__ const float* xsel_ptr(int sel) {
    return (sel < Kc) ? (g_frames + (size_t)sel * Bc * Dc) : g_xbuf[sel - Kc];
}

// Deferred lmhead chunk: iterations [it_lo, it_hi) of pending token t_pend.
// Per-output FMA chain identical to the R13 lmhead (tile xI0 then xI1 into acc).
__device__ __forceinline__ void lmhead_chunk(
    const float* __restrict__ embed, float* __restrict__ out,
    const float* __restrict__ hh, int t_pend, int it_lo, int it_hi,
    int blk, int warp, int lane, int tid,
    float4* wbuf, uint32_t sb, float (*sh0)[4], uint64_t polS)
{
    if (it_lo >= it_hi) return;
    const float* h0 = hh;           const float* h1 = hh + Dc;
    const float* h2 = hh + 2 * Dc;  const float* h3 = hh + 3 * Dc;
    const int xI0 = warp * 64 + lane, xI1 = xI0 + 32;
    float acc[16];
    __syncthreads();   // sh0 safe to reuse
    for (int it = it_lo; it < it_hi; ++it) {
        size_t v0 = (size_t)it * (NBLK * 4) + (size_t)blk * 4;
        const float* wb2 = embed + v0 * Dc;
        ZERO(16);
        ISS4(0, wb2, Dc, xI0, polS);
        ISS4(1, wb2, Dc, xI1, polS);
        {   // tile 0
            float4 b0 = __ldg((const float4*)h0 + xI0);
            float4 b1 = __ldg((const float4*)h1 + xI0);
            float4 b2 = __ldg((const float4*)h2 + xI0);
            float4 b3 = __ldg((const float4*)h3 + xI0);
            cp_wait<1>();
            float4 q0 = wbuf[0 * 32 + lane];
            float4 q1 = wbuf[1 * 32 + lane];
            float4 q2 = wbuf[2 * 32 + lane];
            float4 q3 = wbuf[3 * 32 + lane];
            FMA16(q0, q1, q2, q3, b0, b1, b2, b3);
        }
        {   // tile 1
            float4 b0 = __ldg((const float4*)h0 + xI1);
            float4 b1 = __ldg((const float4*)h1 + xI1);
            float4 b2 = __ldg((const float4*)h2 + xI1);
            float4 b3 = __ldg((const float4*)h3 + xI1);
            cp_wait<0>();
            float4 q0 = wbuf[(4 + 0) * 32 + lane];
            float4 q1 = wbuf[(4 + 1) * 32 + lane];
            float4 q2 = wbuf[(4 + 2) * 32 + lane];
            float4 q3 = wbuf[(4 + 3) * 32 + lane];
            FMA16(q0, q1, q2, q3, b0, b1, b2, b3);
        }
        reduceN<16>(acc, sh0, warp, lane);
        __syncthreads();
        if (tid < 16) {
            int r = tid >> 2, b = tid & 3;
            float s = sh0[tid][0] + sh0[tid][1] + sh0[tid][2] + sh0[tid][3];
            out[((size_t)b * Sc + t_pend) * VOCABc + v0 + r] = s;
        }
        __syncthreads();
    }
}

// ---------------- the whole model as ONE persistent kernel ----------------
__global__ void __launch_bounds__(NTHR, 4) snn_mono_kernel(
    const int* __restrict__ tok, const float* __restrict__ embed,
    const float* __restrict__ norm_w,
    const float* __restrict__ encW, const float* __restrict__ encb,
    const float* __restrict__ decW, const float* __restrict__ decb,
    const float* __restrict__ Win, const float* __restrict__ WbX,
    const float* __restrict__ WaX, const float* __restrict__ WtX,
    const float* __restrict__ WbV, const float* __restrict__ WaV,
    const float* __restrict__ WtV,
    const float* __restrict__ b_beta, const float* __restrict__ b_alpha,
    const float* __restrict__ b_th,
    const float* __restrict__ Wgate, const float* __restrict__ Wskip,
    const float* __restrict__ Wout,
    const float* __restrict__ plif_w, const float* __restrict__ out_vth,
    float* __restrict__ out)
{
    const int blk  = blockIdx.x;
    const int tid  = threadIdx.x;
    const int warp = tid >> 5, lane = tid & 31;
    __shared__ float sh[4][16][4];
    __shared__ float4 cpbuf[4][STAGES * 4 * 32];   // 40KB
    float4* wbuf = cpbuf[warp];
    const uint32_t sb = (uint32_t)__cvta_generic_to_shared(wbuf);
    const uint64_t polS = pol_evict_first();   // one-shot streams (blk1, lmhead)
    const uint64_t polK = pol_evict_last();    // re-read weights (blk2)

    for (int i = blk * NTHR + tid; i < NBc * Bc * DNc; i += NBLK * NTHR) g_Vst[i] = 0.0f;
    for (int i = blk * NTHR + tid; i < NBc * Bc * Dc;  i += NBLK * NTHR) g_u[i]   = 0.0f;
    grid_sync();

    const int xI0 = warp * 64 + lane,  xI1 = xI0 + 32;
    const int vI0 = warp * 128 + lane, vI1 = vI0 + 32, vI2 = vI0 + 64, vI3 = vI0 + 96;
    // lmhead iteration count for this CTA (75 for blk<96, else 74)
    const int nit = ((size_t)74 * (NBLK * 4) + (size_t)blk * 4 < VOCABc) ? 75 : 74;

    int par = 0;
    for (int t = 0; t < Sc; ++t) {
        const float* hhPend = g_hh[(t & 1) ^ 1];   // pending token t-1 (valid for t>0)
        // ================= encoder: 2 rows/block =================
        {
            int j0 = blk * 2;
            const float* e0 = embed + (size_t)__ldg(tok + 0 * Sc + t) * Dc;
            const float* e1 = embed + (size_t)__ldg(tok + 1 * Sc + t) * Dc;
            const float* e2 = embed + (size_t)__ldg(tok + 2 * Sc + t) * Dc;
            const float* e3 = embed + (size_t)__ldg(tok + 3 * Sc + t) * Dc;
            float acc[8];
            ZERO(8);
            passN<2, 2>(encW + (size_t)j0 * Dc, Dc, e0, e1, e2, e3, warp, lane, acc);
            reduceN<8>(acc, sh[0], warp, lane);
            __syncthreads();
            if (tid < 8) {
                int r = tid >> 2, b = tid & 3;
                int j = j0 + r;
                float s = sh[0][tid][0] + sh[0][tid][1] + sh[0][tid][2] + sh[0][tid][3];
                float res = sigmf_(s + encb[j]);
#pragma unroll
                for (int k = 0; k < Kc; ++k) {
                    float bit = (res >= 0.5f) ? 1.0f : 0.0f;
                    g_frames[((size_t)k * Bc + b) * Dc + j] = bit;
                    res = (res - 0.5f * bit) * 2.0f;
                }
                g_decoded[b * Dc + j] = 0.0f;
            }
        }
        grid_sync();

        // ================= K frames x NB blocks =================
        for (int k = 0; k < Kc; ++k) {
            int xin = k;
            for (int i = 0; i < NBc; ++i) {
                // ---- blk1: 4 rows/block, ONE chained pipeline over 20 tiles ----
                {
                    size_t n0 = (size_t)blk * 4;
                    const float* x  = xsel_ptr(xin);
                    const float* Vi = g_Vst + ((size_t)par * NBc + i) * Bc * DNc;
                    float*       Vo = g_Vst + ((size_t)(par ^ 1) * NBc + i) * Bc * DNc;
                    const float* x0 = x;            const float* x1 = x + Dc;
                    const float* x2 = x + 2 * Dc;   const float* x3 = x + 3 * Dc;
                    const float* v0 = Vi;           const float* v1 = Vi + DNc;
                    const float* v2 = Vi + 2 * DNc; const float* v3 = Vi + 3 * DNc;
                    size_t rX = ((size_t)i * DNc + n0) * Dc;
                    size_t rV = ((size_t)i * DNc + n0) * DNc;
                    const float* WBX = WbX + rX; const float* WBV = WbV + rV;
                    const float* WAX = WaX + rX; const float* WAV = WaV + rV;
                    const float* WTX = WtX + rX; const float* WTV = WtV + rV;
                    const float* WIN = Win + rX;
                    float acc[16];

                    ZERO(16);
                    ISS4(0, WBX, Dc,  xI0, polS);
                    ISS4(1, WBX, Dc,  xI1, polS);
                    ISS4(2, WBV, DNc, vI0, polS);
                    ISS4(3, WBV, DNc, vI1, polS); CONS4(0, xI0, x0, x1, x2, x3);
                    ISS4(4, WBV, DNc, vI2, polS); CONS4(1, xI1, x0, x1, x2, x3);
                    ISS4(0, WBV, DNc, vI3, polS); CONS4(2, vI0, v0, v1, v2, v3);
                    ISS4(1, WAX, Dc,  xI0, polS); CONS4(3, vI1, v0, v1, v2, v3);
                    ISS4(2, WAX, Dc,  xI1, polS); CONS4(4, vI2, v0, v1, v2, v3);
                    ISS4(3, WAV, DNc, vI0, polS); CONS4(0, vI3, v0, v1, v2, v3);
                    reduceN<16>(acc, sh[0], warp, lane); ZERO(16);
                    ISS4(4, WAV, DNc, vI1, polS); CONS4(1, xI0, x0, x1, x2, x3);
                    ISS4(0, WAV, DNc, vI2, polS); CONS4(2, xI1, x0, x1, x2, x3);
                    ISS4(1, WAV, DNc, vI3, polS); CONS4(3, vI0, v0, v1, v2, v3);
                    ISS4(2, WTX, Dc,  xI0, polS); CONS4(4, vI1, v0, v1, v2, v3);
                    ISS4(3, WTX, Dc,  xI1, polS); CONS4(0, vI2, v0, v1, v2, v3);
                    ISS4(4, WTV, DNc, vI0, polS); CONS4(1, vI3, v0, v1, v2, v3);
                    reduceN<16>(acc, sh[1], warp, lane); ZERO(16);
                    ISS4(0, WTV, DNc, vI1, polS); CONS4(2, xI0, x0, x1, x2, x3);
                    ISS4(1, WTV, DNc, vI2, polS); CONS4(3, xI1, x0, x1, x2, x3);
                    ISS4(2, WTV, DNc, vI3, polS); CONS4(4, vI0, v0, v1, v2, v3);
                    ISS4(3, WIN, Dc,  xI0, polS); CONS4(0, vI1, v0, v1, v2, v3);
                    ISS4(4, WIN, Dc,  xI1, polS); CONS4(1, vI2, v0, v1, v2, v3);
                    ISS_NONE();                   CONS4(2, vI3, v0, v1, v2, v3);
                    reduceN<16>(acc, sh[2], warp, lane); ZERO(16);
                    ISS_NONE();                   CONS4(3, xI0, x0, x1, x2, x3);
                    ISS_NONE();                   CONS4(4, xI1, x0, x1, x2, x3);
                    reduceN<16>(acc, sh[3], warp, lane);

                    __syncthreads();
                    if (tid < 16) {
                        int r = tid >> 2, b = tid & 3;
                        size_t n = n0 + r;
                        float pB = sh[0][tid][0] + sh[0][tid][1] + sh[0][tid][2] + sh[0][tid][3];
                        float pA = sh[1][tid][0] + sh[1][tid][1] + sh[1][tid][2] + sh[1][tid][3];
                        float pT = sh[2][tid][0] + sh[2][tid][1] + sh[2][tid][2] + sh[2][tid][3];
                        float pI = sh[3][tid][0] + sh[3][tid][1] + sh[3][tid][2] + sh[3][tid][3];
                        float beta  = sigmf_(pB + b_beta[(size_t)i * DNc + n]);
                        float alpha = sigmf_(pA + b_alpha[(size_t)i * DNc + n]);
                        float vth   = 0.1f + softplusf_(pT + b_th[(size_t)i * DNc + n]);
                        float vold  = Vi[(size_t)b * DNc + n];
                        float vnew  = beta * vold + alpha * pI;
                        float spv   = ((vnew - vth) >= 0.0f) ? 1.0f : 0.0f;
                        Vo[(size_t)b * DNc + n]   = vnew - spv * vth;
                        g_sp[(size_t)b * DNc + n] = spv;
                    }
                }
                // deferred lmhead chunk (slot 2*(k*4+i)) for token t-1
                if (t > 0) {
                    int s = (k * 4 + i) * 2;
                    lmhead_chunk(embed, out, hhPend, t - 1,
                                 (s * nit) >> 6, ((s + 1) * nit) >> 6,
                                 blk, warp, lane, tid, wbuf, sb, sh[0], polS);
                }
                grid_sync();

                // ---- blk2: 2 rows/block, chained pipeline over 8 tiles ----
                {
                    int xo = Kc + (i & 1);
                    size_t j0 = (size_t)blk * 2;
                    const float* x = xsel_ptr(xin);
                    float* xout = g_xbuf[xo - Kc];
                    const float* x0 = x;           const float* x1 = x + Dc;
                    const float* x2 = x + 2 * Dc;  const float* x3 = x + 3 * Dc;
                    const float* s0 = g_sp;            const float* s1 = g_sp + DNc;
                    const float* s2 = g_sp + 2 * DNc;  const float* s3 = g_sp + 3 * DNc;
                    size_t rD = ((size_t)i * Dc + j0) * Dc;
                    size_t rN = ((size_t)i * Dc + j0) * DNc;
                    const float* WG = Wgate + rD;
                    const float* WS = Wskip + rD;
                    const float* WO = Wout + rN;
                    float acc[8];

                    ZERO(8);
                    ISS2(0, WG, Dc,  xI0, polK);
                    ISS2(1, WG, Dc,  xI1, polK);
                    ISS2(2, WS, Dc,  xI0, polK);
                    ISS2(3, WS, Dc,  xI1, polK); CONS2(0, xI0, x0, x1, x2, x3);
                    ISS2(4, WO, DNc, vI0, polK); CONS2(1, xI1, x0, x1, x2, x3);
                    reduceN<8>(acc, sh[0], warp, lane); ZERO(8);
                    ISS2(0, WO, DNc, vI1, polK); CONS2(2, xI0, x0, x1, x2, x3);
                    ISS2(1, WO, DNc, vI2, polK); CONS2(3, xI1, x0, x1, x2, x3);
                    reduceN<8>(acc, sh[1], warp, lane); ZERO(8);
                    ISS2(2, WO, DNc, vI3, polK); CONS2(4, vI0, s0, s1, s2, s3);
                    ISS_NONE();                  CONS2(0, vI1, s0, s1, s2, s3);
                    ISS_NONE();                  CONS2(1, vI2, s0, s1, s2, s3);
                    ISS_NONE();                  CONS2(2, vI3, s0, s1, s2, s3);
                    reduceN<8>(acc, sh[2], warp, lane);

                    __syncthreads();
                    if (tid < 8) {
                        int r = tid >> 2, b = tid & 3;
                        size_t j = j0 + r;
                        float g  = sh[0][tid][0] + sh[0][tid][1] + sh[0][tid][2] + sh[0][tid][3];
                        float sk = sh[1][tid][0] + sh[1][tid][1] + sh[1][tid][2] + sh[1][tid][3];
                        float o  = sh[2][tid][0] + sh[2][tid][1] + sh[2][tid][2] + sh[2][tid][3];
                        float cur = sigmf_(g) * o + sk;
                        float tau = sigmf_(plif_w[i]);
                        float vt  = out_vth[i];
                        size_t ui = ((size_t)i * Bc + b) * Dc + j;
                        float uu = g_u[ui];
                        uu = uu + (cur - uu) * tau;
                        float so = ((uu - vt) >= 0.0f) ? 1.0f : 0.0f;
                        g_u[ui] = (1.0f - so) * uu;
                        xout[(size_t)b * Dc + j] = so;
                        if (i == NBc - 1) {
                            float wk = 1.0f / (float)(1 << (k + 1));
                            g_decoded[(size_t)b * Dc + j] += wk * so;
                        }
                    }
                    xin = xo;
                }
                // deferred lmhead chunk (slot 2*(k*4+i)+1) for token t-1
                if (t > 0) {
                    int s = (k * 4 + i) * 2 + 1;
                    lmhead_chunk(embed, out, hhPend, t - 1,
                                 (s * nit) >> 6, ((s + 1) * nit) >> 6,
                                 blk, warp, lane, tid, wbuf, sb, sh[0], polS);
                }
                grid_sync();
            }
            par ^= 1;
        }

        // ================= decoder: 2 rows/block =================
        {
            size_t j0 = (size_t)blk * 2;
            float* hh = g_hh[t & 1];
            const float* d0 = g_decoded;           const float* d1 = g_decoded + Dc;
            const float* d2 = g_decoded + 2 * Dc;  const float* d3 = g_decoded + 3 * Dc;
            float acc[8];
            ZERO(8);
            passN<2, 2>(decW + j0 * Dc, Dc, d0, d1, d2, d3, warp, lane, acc);
            reduceN<8>(acc, sh[0], warp, lane);
            __syncthreads();
            if (tid < 8) {
                int r = tid >> 2, b = tid & 3;
                size_t j = j0 + r;
                float s = sh[0][tid][0] + sh[0][tid][1] + sh[0][tid][2] + sh[0][tid][3];
                hh[(size_t)b * Dc + j] = s + decb[j];
            }
        }
        grid_sync();

        // ================= RMSNorm (block 0 only) =================
        if (blk == 0) {
            float* hh = g_hh[t & 1];
            __shared__ float srstd[Bc];
            if (warp < Bc) {
                float s = 0.0f;
                for (int j = lane; j < Dc; j += 32) {
                    float v = hh[warp * Dc + j];
                    s = fmaf(v, v, s);
                }
                s = warp_sum(s);
                if (lane == 0) srstd[warp] = 1.0f / sqrtf(s / (float)Dc + 1e-6f);
            }
            __syncthreads();
            for (int idx = tid; idx < Bc * Dc; idx += NTHR) {
                hh[idx] = hh[idx] * norm_w[idx & (Dc - 1)] * srstd[idx >> 10];
            }
        }
        grid_sync();
        // lmhead(t) deferred into token t+1's phases (tail below for t = Sc-1)
    }

    // ================= tail: lmhead for the last token (chained) =================
    {
        const float* hh = g_hh[(Sc - 1) & 1];
        const float* h0 = hh;           const float* h1 = hh + Dc;
        const float* h2 = hh + 2 * Dc;  const float* h3 = hh + 3 * Dc;
        const int TT = nit * 2;
        float acc[16];
        ZERO(16);
#pragma unroll
        for (int tau = 0; tau < PFD; ++tau) {
            int it2 = tau >> 1, sub = tau & 1;
            const float* wb2 = embed + ((size_t)it2 * (NBLK * 4) + (size_t)blk * 4) * Dc;
            ISS4(tau, wb2, Dc, xI0 + sub * 32, polS);
        }
        for (int tau = 0; tau < TT; ++tau) {
            int tf = tau + PFD;
            if (tf < TT) {
                int it2 = tf >> 1, sub = tf & 1;
                const float* wb2 = embed + ((size_t)it2 * (NBLK * 4) + (size_t)blk * 4) * Dc;
                ISS4(tf % STAGES, wb2, Dc, xI0 + sub * 32, polS);
            } else {
                ISS_NONE();
            }
            CONS4(tau % STAGES, xI0 + (tau & 1) * 32, h0, h1, h2, h3);
            if (tau & 1) {
                reduceN<16>(acc, sh[0], warp, lane);
                __syncthreads();
                if (tid < 16) {
                    int r = tid >> 2, b = tid & 3;
                    size_t v0 = (size_t)(tau >> 1) * (NBLK * 4) + (size_t)blk * 4;
                    float s = sh[0][tid][0] + sh[0][tid][1] + sh[0][tid][2] + sh[0][tid][3];
                    out[((size_t)b * Sc + (Sc - 1)) * VOCABc + v0 + r] = s;
                }
                __syncthreads();
                ZERO(16);
            }
        }
    }
}

// ---------------- host driver: ONE graph node ----------------
extern "C" void kernel_launch(void* const* d_in, const int* in_sizes, int n_in,
                              void* d_out, int out_size)
{
    (void)in_sizes; (void)n_in; (void)out_size;
    snn_mono_kernel<<<NBLK, NTHR>>>(
        (const int*)d_in[0],  (const float*)d_in[1],  (const float*)d_in[2],
        (const float*)d_in[3], (const float*)d_in[4], (const float*)d_in[5],
        (const float*)d_in[6], (const float*)d_in[7], (const float*)d_in[8],
        (const float*)d_in[9], (const float*)d_in[10], (const float*)d_in[11],
        (const float*)d_in[12], (const float*)d_in[13], (const float*)d_in[14],
        (const float*)d_in[15], (const float*)d_in[16], (const float*)d_in[17],
        (const float*)d_in[18], (const float*)d_in[19], (const float*)d_in[20],
        (const float*)d_in[21], (float*)d_out);
}